// round 11
// baseline (speedup 1.0000x reference)
#include <cuda_runtime.h>
#include <cuda_bf16.h>
#include <math.h>

// Problem constants
#define BT   2048      // B*T
#define D    2048
#define H    4
#define TOPK 8
#define DK   64
#define NE   16384     // E
#define NK   128
#define QN   512       // 2*H*DK

// ---- packed f32x2 ops (Blackwell sm_103a; FFMA2 only reachable via PTX) ----
#define FMA_F32X2(d, a, b, c) \
    asm("fma.rn.f32x2 %0, %1, %2, %3;" : "=l"(d) : "l"(a), "l"(b), "l"(c))
#define ADD_F32X2(d, a, b) \
    asm("add.rn.f32x2 %0, %1, %2;" : "=l"(d) : "l"(a), "l"(b))
#define SUB_F32X2(d, a, b) \
    asm("sub.rn.f32x2 %0, %1, %2;" : "=l"(d) : "l"(a), "l"(b))
#define PACK_F32X2(out, lo, hi) \
    asm("mov.b64 %0, {%1, %2};" : "=l"(out) : "f"(lo), "f"(hi))
#define UNPACK_F32X2(lo, hi, in) \
    asm("mov.b64 {%0, %1}, %2;" : "=f"(lo), "=f"(hi) : "l"(in))

// ---- mbarrier / bulk-async helpers ----
__device__ __forceinline__ unsigned smem_u32(const void* p) {
    unsigned a;
    asm("{ .reg .u64 t; cvta.to.shared.u64 t, %1; cvt.u32.u64 %0, t; }"
        : "=r"(a) : "l"(p));
    return a;
}
#define MBAR_INIT(addr, cnt) \
    asm volatile("mbarrier.init.shared.b64 [%0], %1;" :: "r"(addr), "r"(cnt) : "memory")
#define MBAR_EXPECT_TX(addr, bytes) \
    asm volatile("mbarrier.arrive.expect_tx.shared.b64 _, [%0], %1;" :: "r"(addr), "r"(bytes) : "memory")
#define MBAR_ARRIVE(addr) \
    asm volatile("mbarrier.arrive.shared.b64 _, [%0];" :: "r"(addr) : "memory")
#define BULK_G2S(dst, src, bytes, mbar) \
    asm volatile("cp.async.bulk.shared::cluster.global.mbarrier::complete_tx::bytes [%0], [%1], %2, [%3];" \
                 :: "r"(dst), "l"(src), "r"(bytes), "r"(mbar) : "memory")

__device__ __forceinline__ void mbar_wait(unsigned addr, unsigned parity) {
    asm volatile(
        "{\n\t.reg .pred P;\n"
        "WL%=:\n\t"
        "mbarrier.try_wait.parity.acquire.cta.shared::cta.b64 P, [%0], %1, 0x989680;\n\t"
        "@P bra WD%=;\n\t"
        "bra WL%=;\n"
        "WD%=:\n\t}"
        :: "r"(addr), "r"(parity) : "memory");
}

// ---------------- scratch (device globals, no alloc) ----------------
__device__ float g_qp[2][BT * QN];         // split-K partials, 8 MB
__device__ float g_scores[BT * H * TOPK];  // 256 KB
__device__ int   g_indices[BT * H * TOPK];

// =====================================================================
// Kernel 1: q = x @ Wq   (FP32 SGEMM, M=2048, N=512, K=2048)
// Split-K=2 (grid.z), BM=64 BN=64 BK=16, 256 threads, 4x4/thread.
// Inner product in packed f32x2 (FFMA2), Kahan chunk merge in f32x2.
// =====================================================================
__global__ __launch_bounds__(256) void qproj_kernel(const float* __restrict__ A,
                                                    const float* __restrict__ B) {
    const int Kd = D, N = QN;
    const int KSPLIT = Kd / 2;       // 1024
    const int NCH = KSPLIT / 16;     // 64 chunks

    __shared__ float As[2][16][68];  // transposed, padded
    __shared__ float Bs[2][16][64];

    int tid = threadIdx.x;
    int tx = tid & 15;               // col group (4 cols each)
    int ty = tid >> 4;               // row group (4 rows each)
    int row0 = blockIdx.y * 64;
    int col0 = blockIdx.x * 64;
    int kbase = blockIdx.z * KSPLIT;

    int ar = tid >> 2, ac4 = tid & 3;
    int br = tid >> 4, bc4 = tid & 15;

    const float* Aptr = A + (size_t)(row0 + ar) * Kd + kbase + ac4 * 4;
    const float* Bptr = B + (size_t)(kbase + br) * N + col0 + bc4 * 4;

    // accumulators: 4 rows x 2 column-pairs, packed f32x2
    unsigned long long acc2[4][2], cmp2[4][2];
#pragma unroll
    for (int i = 0; i < 4; i++)
#pragma unroll
        for (int jp = 0; jp < 2; jp++) { acc2[i][jp] = 0ull; cmp2[i][jp] = 0ull; }

    // preload chunk 0 into buffer 0
    float4 av = *(const float4*)Aptr;
    float4 bv = *(const float4*)Bptr;
    As[0][ac4 * 4 + 0][ar] = av.x;
    As[0][ac4 * 4 + 1][ar] = av.y;
    As[0][ac4 * 4 + 2][ar] = av.z;
    As[0][ac4 * 4 + 3][ar] = av.w;
    *(float4*)&Bs[0][br][bc4 * 4] = bv;
    __syncthreads();

    int buf = 0;
    for (int c = 0; c < NCH; c++) {
        // prefetch next chunk into registers (overlaps with compute)
        if (c + 1 < NCH) {
            Aptr += 16;
            Bptr += (size_t)16 * N;
            av = *(const float4*)Aptr;
            bv = *(const float4*)Bptr;
        }

        unsigned long long sub2[4][2];
#pragma unroll
        for (int i = 0; i < 4; i++)
#pragma unroll
            for (int jp = 0; jp < 2; jp++) sub2[i][jp] = 0ull;

#pragma unroll
        for (int k = 0; k < 16; k++) {
            float4 a = *(const float4*)&As[buf][k][ty * 4];
            const unsigned long long* bp = (const unsigned long long*)&Bs[buf][k][tx * 4];
            unsigned long long b0 = bp[0], b1 = bp[1];

            unsigned long long ax, ay, az, aw;
            PACK_F32X2(ax, a.x, a.x);
            PACK_F32X2(ay, a.y, a.y);
            PACK_F32X2(az, a.z, a.z);
            PACK_F32X2(aw, a.w, a.w);

            FMA_F32X2(sub2[0][0], ax, b0, sub2[0][0]);
            FMA_F32X2(sub2[0][1], ax, b1, sub2[0][1]);
            FMA_F32X2(sub2[1][0], ay, b0, sub2[1][0]);
            FMA_F32X2(sub2[1][1], ay, b1, sub2[1][1]);
            FMA_F32X2(sub2[2][0], az, b0, sub2[2][0]);
            FMA_F32X2(sub2[2][1], az, b1, sub2[2][1]);
            FMA_F32X2(sub2[3][0], aw, b0, sub2[3][0]);
            FMA_F32X2(sub2[3][1], aw, b1, sub2[3][1]);
        }

        // Kahan merge of chunk sums (packed, per-lane identical to scalar)
#pragma unroll
        for (int i = 0; i < 4; i++)
#pragma unroll
            for (int jp = 0; jp < 2; jp++) {
                unsigned long long y, t, d;
                SUB_F32X2(y, sub2[i][jp], cmp2[i][jp]);   // y = sub - cmp
                ADD_F32X2(t, acc2[i][jp], y);             // t = acc + y
                SUB_F32X2(d, t, acc2[i][jp]);             // d = t - acc
                SUB_F32X2(cmp2[i][jp], d, y);             // cmp = d - y
                acc2[i][jp] = t;
            }

        // stage prefetched chunk into the other buffer
        if (c + 1 < NCH) {
            int nb = buf ^ 1;
            As[nb][ac4 * 4 + 0][ar] = av.x;
            As[nb][ac4 * 4 + 1][ar] = av.y;
            As[nb][ac4 * 4 + 2][ar] = av.z;
            As[nb][ac4 * 4 + 3][ar] = av.w;
            *(float4*)&Bs[nb][br][bc4 * 4] = bv;
            __syncthreads();
            buf = nb;
        }
    }

    float* qdst = g_qp[blockIdx.z];
#pragma unroll
    for (int i = 0; i < 4; i++) {
        int row = row0 + ty * 4 + i;
        float4 v;
        UNPACK_F32X2(v.x, v.y, acc2[i][0]);
        UNPACK_F32X2(v.z, v.w, acc2[i][1]);
        *(float4*)&qdst[(size_t)row * N + col0 + tx * 4] = v;
    }
}

// =====================================================================
// Kernel 2: sim = q . keys (Kahan), dual top-8, 64-combine, final top-8
// =====================================================================
#define K2_SMEM (65536 + 32 * 132 * 4 + 32 * 258 * 4)

__global__ __launch_bounds__(256) void router_kernel(const float* __restrict__ keys) {
    extern __shared__ float smem[];
    float* ks = smem;               // [2][128][64]  16384 floats
    float* qs = ks + 16384;         // [32][132]      4224 floats
    float* sm = qs + 32 * 132;      // [32][2][129]   8256 floats

    int h    = blockIdx.y;
    int tok0 = blockIdx.x * 32;
    int tid  = threadIdx.x;

    // ---- load keys for this head: keys[h][k][s][dk] -> ks[s][k][dk]
    const float4* kg = (const float4*)keys;
    float4* ks4 = (float4*)ks;
#pragma unroll
    for (int i = 0; i < 16; i++) {
        int u = tid + i * 256;          // 4096 float4s
        int dk4 = u & 15;
        int s   = (u >> 4) & 1;
        int k   = u >> 5;
        ks4[(s * 128 + k) * 16 + dk4] = kg[((h * 128 + k) * 2 + s) * 16 + dk4];
    }

    // ---- load q tile (sum of split-K partials): -> qs[t][c] (stride 132)
    const float4* qg0 = (const float4*)g_qp[0];
    const float4* qg1 = (const float4*)g_qp[1];
    float4* qs4 = (float4*)qs;
#pragma unroll
    for (int i = 0; i < 4; i++) {
        int u = tid + i * 256;          // 1024 float4s
        int c4 = u & 31;
        int t  = u >> 5;
        size_t gidx = (size_t)(tok0 + t) * 128 + h * 32 + c4;
        float4 a = qg0[gidx], b = qg1[gidx];
        qs4[t * 33 + c4] = make_float4(a.x + b.x, a.y + b.y, a.z + b.z, a.w + b.w);
    }
    __syncthreads();

    // ---- sims: warp w: side=w>>2, keys [(w&3)*32, +32), lane = token
    int w = tid >> 5, lane = tid & 31;
    int side  = w >> 2;
    int kbase = (w & 3) * 32;
    const float4* qrow = (const float4*)qs + lane * 33 + side * 16;
    for (int kk = 0; kk < 32; kk++) {
        int k = kbase + kk;
        const float4* krow = (const float4*)ks + (side * 128 + k) * 16;
        float acc = 0.f, comp = 0.f;
#pragma unroll
        for (int c4 = 0; c4 < 16; c4++) {
            float4 kv = krow[c4];   // broadcast across lanes
            float4 qv = qrow[c4];   // conflict-free (stride 33 f4)
            float term = kv.x * qv.x + kv.y * qv.y + kv.z * qv.z + kv.w * qv.w;
            float y = term - comp;
            float t = acc + y;
            comp = (t - acc) - y;
            acc = t;
        }
        sm[lane * 258 + side * 129 + k] = acc;
    }
    __syncthreads();

    // ---- top-k (32 threads, one token each; stable like jax.lax.top_k)
    if (tid < 32) {
        const float NEG = -3.4e38f;
        float s1[TOPK], s2[TOPK], fs[TOPK];
        int   i1[TOPK], i2[TOPK], fi[TOPK];
#pragma unroll
        for (int r = 0; r < TOPK; r++) { s1[r] = NEG; s2[r] = NEG; fs[r] = NEG; i1[r] = 0; i2[r] = 0; fi[r] = 0; }

        const float* row1 = sm + tid * 258;
        const float* row2 = row1 + 129;
        for (int k = 0; k < NK; k++) {
            float v = row1[k];
            if (v > s1[TOPK - 1]) {
                int p = TOPK - 1;
                while (p > 0 && v > s1[p - 1]) { s1[p] = s1[p - 1]; i1[p] = i1[p - 1]; p--; }
                s1[p] = v; i1[p] = k;
            }
        }
        for (int k = 0; k < NK; k++) {
            float v = row2[k];
            if (v > s2[TOPK - 1]) {
                int p = TOPK - 1;
                while (p > 0 && v > s2[p - 1]) { s2[p] = s2[p - 1]; i2[p] = i2[p - 1]; p--; }
                s2[p] = v; i2[p] = k;
            }
        }
        // combine K*K in flattened order i*K+j (matches jax reshape/stability)
        for (int i = 0; i < TOPK; i++) {
            for (int j = 0; j < TOPK; j++) {
                float v = s1[i] + s2[j];
                if (v > fs[TOPK - 1]) {
                    int idx = i1[i] * NK + i2[j];
                    int p = TOPK - 1;
                    while (p > 0 && v > fs[p - 1]) { fs[p] = fs[p - 1]; fi[p] = fi[p - 1]; p--; }
                    fs[p] = v; fi[p] = idx;
                }
            }
        }
        int base = ((tok0 + tid) * H + h) * TOPK;
#pragma unroll
        for (int r = 0; r < TOPK; r++) {
            g_scores[base + r]  = fs[r];
            g_indices[base + r] = fi[r];
        }
    }
}

// =====================================================================
// Kernel 3 (v4): bulk-async gather pipeline
// 2 tokens/block, 256 threads, 3-stage ring of 8 rows x 8KB.
// Rounds 0..7: down rows (warp w -> token w&1, expert r*4+(w>>1))
// Rounds 8..15: up rows (all threads accumulate all 8 slots)
// Producer tid0: expect_tx + 8x cp.async.bulk per stage, 3 rounds ahead.
// =====================================================================
#define NSTAGE 3
#define K3_SMEM (NSTAGE * 8 * 8192)   // 196608 bytes dynamic

__global__ __launch_bounds__(256) void expert_kernel(const float* __restrict__ x,
                                                     const float* __restrict__ e_down,
                                                     const float* __restrict__ e_up,
                                                     float* __restrict__ out) {
    extern __shared__ float ring[];                 // [NSTAGE][8][2048]
    __shared__ float xs[2 * D];                     // 16 KB
    __shared__ float hid[2][H * TOPK];
    __shared__ int   eidx[2][H * TOPK];
    __shared__ alignas(8) unsigned long long mbar[2 * NSTAGE];  // full[s], empty[s]

    int tok0 = blockIdx.x * 2;
    int tid  = threadIdx.x;
    int w = tid >> 5, lane = tid & 31;

    // load both token x rows + indices
    const float4* xg = (const float4*)(x + (size_t)tok0 * D);
    float4* xs4 = (float4*)xs;
#pragma unroll
    for (int i = 0; i < 4; i++) xs4[tid + i * 256] = xg[tid + i * 256];
    if (tid < 64) eidx[tid >> 5][tid & 31] = g_indices[tok0 * 32 + tid];

    unsigned full_a[NSTAGE], empty_a[NSTAGE];
#pragma unroll
    for (int s = 0; s < NSTAGE; s++) {
        full_a[s]  = smem_u32(&mbar[s]);
        empty_a[s] = smem_u32(&mbar[NSTAGE + s]);
    }
    if (tid == 0) {
#pragma unroll
        for (int s = 0; s < NSTAGE; s++) {
            MBAR_INIT(full_a[s], 1);
            MBAR_INIT(empty_a[s], 256);
        }
    }
    __syncthreads();

    // producer: issue one stage (8 rows) for round r2 into stage s
    auto issue_round = [&](int r2, int s) {
        MBAR_EXPECT_TX(full_a[s], 65536u);
#pragma unroll
        for (int ws = 0; ws < 8; ws++) {
            int t = ws & 1;
            const float* src;
            if (r2 < 8) src = e_down + (size_t)eidx[t][r2 * 4 + (ws >> 1)] * D;
            else        src = e_up   + (size_t)eidx[t][(r2 - 8) * 4 + (ws >> 1)] * D;
            unsigned dst = smem_u32(ring + (s * 8 + ws) * 2048);
            unsigned nb = 8192u;
            BULK_G2S(dst, src, nb, full_a[s]);
        }
    };
    if (tid == 0) {
        issue_round(0, 0);
        issue_round(1, 1);
        issue_round(2, 2);
    }

    float4 a00 = make_float4(0, 0, 0, 0), a01 = a00, a10 = a00, a11 = a00;
    int t_mine = w & 1;
    const float4* xrow = xs4 + t_mine * 512;

    for (int r = 0; r < 16; r++) {
        int s = r % NSTAGE;
        unsigned par = (unsigned)((r / NSTAGE) & 1);
        mbar_wait(full_a[s], par);

        if (r < 8) {
            // down: warp w dots slot w against x[t_mine]
            int e = r * 4 + (w >> 1);
            const float4* row4 = (const float4*)(ring + (s * 8 + w) * 2048);
            float acc0 = 0.f, acc1 = 0.f;
#pragma unroll
            for (int i = 0; i < 16; i += 2) {
                float4 ev0 = row4[lane + 32 * i];
                float4 ev1 = row4[lane + 32 * (i + 1)];
                float4 qv0 = xrow[lane + 32 * i];
                float4 qv1 = xrow[lane + 32 * (i + 1)];
                acc0 += ev0.x * qv0.x + ev0.y * qv0.y + ev0.z * qv0.z + ev0.w * qv0.w;
                acc1 += ev1.x * qv1.x + ev1.y * qv1.y + ev1.z * qv1.z + ev1.w * qv1.w;
            }
            float acc = acc0 + acc1;
#pragma unroll
            for (int o = 16; o > 0; o >>= 1) acc += __shfl_xor_sync(0xffffffffu, acc, o);
            if (lane == 0) {
                float sc = g_scores[(tok0 + t_mine) * 32 + e];
                float g  = acc / (1.f + __expf(-acc));     // silu
                hid[t_mine][e] = g * fmaxf(sc, 0.f);       // * relu(score)
            }
        } else {
            // up: all threads accumulate all 8 slots
            int rr = r - 8;
#pragma unroll
            for (int w2 = 0; w2 < 8; w2++) {
                int t2 = w2 & 1;
                int e2 = rr * 4 + (w2 >> 1);
                float g = hid[t2][e2];
                const float4* row4 = (const float4*)(ring + (s * 8 + w2) * 2048);
                float4 u0 = row4[tid], u1 = row4[tid + 256];
                if (t2 == 0) {
                    a00.x += g * u0.x; a00.y += g * u0.y; a00.z += g * u0.z; a00.w += g * u0.w;
                    a01.x += g * u1.x; a01.y += g * u1.y; a01.z += g * u1.z; a01.w += g * u1.w;
                } else {
                    a10.x += g * u0.x; a10.y += g * u0.y; a10.z += g * u0.z; a10.w += g * u0.w;
                    a11.x += g * u1.x; a11.y += g * u1.y; a11.z += g * u1.z; a11.w += g * u1.w;
                }
            }
        }

        MBAR_ARRIVE(empty_a[s]);                     // all 256 threads
        if (tid == 0 && r + NSTAGE < 16) {
            mbar_wait(empty_a[s], par);              // all readers done with stage s
            issue_round(r + NSTAGE, s);
        }
        if (r == 7) __syncthreads();                 // hid visibility for up rounds
    }

    float4* og = (float4*)(out + (size_t)tok0 * D);
    og[tid]       = a00;
    og[tid + 256] = a01;
    og[tid + 512] = a10;
    og[tid + 768] = a11;
}

// =====================================================================
// launch
// =====================================================================
extern "C" void kernel_launch(void* const* d_in, const int* in_sizes, int n_in,
                              void* d_out, int out_size) {
    const float* x      = (const float*)d_in[0];
    const float* Wq     = (const float*)d_in[1];
    const float* keys   = (const float*)d_in[2];
    const float* e_down = (const float*)d_in[3];
    const float* e_up   = (const float*)d_in[4];
    float* out = (float*)d_out;

    cudaFuncSetAttribute(router_kernel, cudaFuncAttributeMaxDynamicSharedMemorySize, K2_SMEM);
    cudaFuncSetAttribute(expert_kernel, cudaFuncAttributeMaxDynamicSharedMemorySize, K3_SMEM);

    qproj_kernel<<<dim3(QN / 64, BT / 64, 2), 256>>>(x, Wq);
    router_kernel<<<dim3(BT / 32, H), 256, K2_SMEM>>>(keys);
    expert_kernel<<<BT / 2, 256, K3_SMEM>>>(x, e_down, e_up, out);
}

// round 15
// speedup vs baseline: 1.0196x; 1.0196x over previous
#include <cuda_runtime.h>
#include <cuda_bf16.h>
#include <math.h>

// Problem constants
#define BT   2048      // B*T
#define D    2048
#define H    4
#define TOPK 8
#define DK   64
#define NE   16384     // E
#define NK   128
#define QN   512       // 2*H*DK

#define KSPLITS 4

// ---- packed f32x2 ops (Blackwell sm_103a; FFMA2 only reachable via PTX) ----
#define FMA_F32X2(d, a, b, c) \
    asm("fma.rn.f32x2 %0, %1, %2, %3;" : "=l"(d) : "l"(a), "l"(b), "l"(c))
#define ADD_F32X2(d, a, b) \
    asm("add.rn.f32x2 %0, %1, %2;" : "=l"(d) : "l"(a), "l"(b))
#define SUB_F32X2(d, a, b) \
    asm("sub.rn.f32x2 %0, %1, %2;" : "=l"(d) : "l"(a), "l"(b))
#define PACK_F32X2(out, lo, hi) \
    asm("mov.b64 %0, {%1, %2};" : "=l"(out) : "f"(lo), "f"(hi))
#define UNPACK_F32X2(lo, hi, in) \
    asm("mov.b64 {%0, %1}, %2;" : "=f"(lo), "=f"(hi) : "l"(in))

// ---------------- scratch (device globals, no alloc) ----------------
__device__ float g_qp[KSPLITS][BT * QN];   // split-K partials, 16 MB
__device__ float g_scores[BT * H * TOPK];  // 256 KB
__device__ int   g_indices[BT * H * TOPK];

// =====================================================================
// Kernel 1: q = x @ Wq   (FP32 SGEMM, M=2048, N=512, K=2048)
// Split-K=4 (grid.z), BM=64 BN=128 BK=16, 256 threads, 4x8/thread.
// Inner product in packed f32x2 (FFMA2), Kahan chunk merge in f32x2.
// =====================================================================
__global__ __launch_bounds__(256) void qproj_kernel(const float* __restrict__ A,
                                                    const float* __restrict__ B) {
    const int Kd = D, N = QN;
    const int KSPLIT = Kd / KSPLITS;   // 512
    const int NCH = KSPLIT / 16;       // 32 chunks

    __shared__ float As[2][16][68];    // transposed, padded
    __shared__ float Bs[2][16][128];

    int tid = threadIdx.x;
    int tx = tid & 15;                 // col group (8 cols each)
    int ty = tid >> 4;                 // row group (4 rows each)
    int row0 = blockIdx.y * 64;
    int col0 = blockIdx.x * 128;
    int kbase = blockIdx.z * KSPLIT;

    int ar = tid >> 2, ac4 = tid & 3;  // A tile: 64 rows x 4 f4-cols
    int br = tid >> 4, bc4 = tid & 15; // B tile: 16 rows x 16 f4-cols (x2 halves)

    const float* Aptr = A + (size_t)(row0 + ar) * Kd + kbase + ac4 * 4;
    const float* Bptr = B + (size_t)(kbase + br) * N + col0 + bc4 * 4;

    // accumulators: 4 rows x 4 column-pairs (8 cols), packed f32x2
    unsigned long long acc2[4][4], cmp2[4][4];
#pragma unroll
    for (int i = 0; i < 4; i++)
#pragma unroll
        for (int jp = 0; jp < 4; jp++) { acc2[i][jp] = 0ull; cmp2[i][jp] = 0ull; }

    // preload chunk 0 into buffer 0
    float4 av  = *(const float4*)Aptr;
    float4 bv0 = *(const float4*)Bptr;
    float4 bv1 = *(const float4*)(Bptr + 64);
    As[0][ac4 * 4 + 0][ar] = av.x;
    As[0][ac4 * 4 + 1][ar] = av.y;
    As[0][ac4 * 4 + 2][ar] = av.z;
    As[0][ac4 * 4 + 3][ar] = av.w;
    *(float4*)&Bs[0][br][bc4 * 4]      = bv0;
    *(float4*)&Bs[0][br][64 + bc4 * 4] = bv1;
    __syncthreads();

    int buf = 0;
    for (int c = 0; c < NCH; c++) {
        // prefetch next chunk into registers (overlaps with compute)
        if (c + 1 < NCH) {
            Aptr += 16;
            Bptr += (size_t)16 * N;
            av  = *(const float4*)Aptr;
            bv0 = *(const float4*)Bptr;
            bv1 = *(const float4*)(Bptr + 64);
        }

        unsigned long long sub2[4][4];
#pragma unroll
        for (int i = 0; i < 4; i++)
#pragma unroll
            for (int jp = 0; jp < 4; jp++) sub2[i][jp] = 0ull;

#pragma unroll
        for (int k = 0; k < 16; k++) {
            float4 a = *(const float4*)&As[buf][k][ty * 4];
            const unsigned long long* bp =
                (const unsigned long long*)&Bs[buf][k][tx * 8];
            unsigned long long b0 = bp[0], b1 = bp[1], b2 = bp[2], b3 = bp[3];

            unsigned long long ax, ay, az, aw;
            PACK_F32X2(ax, a.x, a.x);
            PACK_F32X2(ay, a.y, a.y);
            PACK_F32X2(az, a.z, a.z);
            PACK_F32X2(aw, a.w, a.w);

            FMA_F32X2(sub2[0][0], ax, b0, sub2[0][0]);
            FMA_F32X2(sub2[0][1], ax, b1, sub2[0][1]);
            FMA_F32X2(sub2[0][2], ax, b2, sub2[0][2]);
            FMA_F32X2(sub2[0][3], ax, b3, sub2[0][3]);
            FMA_F32X2(sub2[1][0], ay, b0, sub2[1][0]);
            FMA_F32X2(sub2[1][1], ay, b1, sub2[1][1]);
            FMA_F32X2(sub2[1][2], ay, b2, sub2[1][2]);
            FMA_F32X2(sub2[1][3], ay, b3, sub2[1][3]);
            FMA_F32X2(sub2[2][0], az, b0, sub2[2][0]);
            FMA_F32X2(sub2[2][1], az, b1, sub2[2][1]);
            FMA_F32X2(sub2[2][2], az, b2, sub2[2][2]);
            FMA_F32X2(sub2[2][3], az, b3, sub2[2][3]);
            FMA_F32X2(sub2[3][0], aw, b0, sub2[3][0]);
            FMA_F32X2(sub2[3][1], aw, b1, sub2[3][1]);
            FMA_F32X2(sub2[3][2], aw, b2, sub2[3][2]);
            FMA_F32X2(sub2[3][3], aw, b3, sub2[3][3]);
        }

        // Kahan merge of chunk sums (packed, per-lane identical to scalar)
#pragma unroll
        for (int i = 0; i < 4; i++)
#pragma unroll
            for (int jp = 0; jp < 4; jp++) {
                unsigned long long y, t, d;
                SUB_F32X2(y, sub2[i][jp], cmp2[i][jp]);   // y = sub - cmp
                ADD_F32X2(t, acc2[i][jp], y);             // t = acc + y
                SUB_F32X2(d, t, acc2[i][jp]);             // d = t - acc
                SUB_F32X2(cmp2[i][jp], d, y);             // cmp = d - y
                acc2[i][jp] = t;
            }

        // stage prefetched chunk into the other buffer
        if (c + 1 < NCH) {
            int nb = buf ^ 1;
            As[nb][ac4 * 4 + 0][ar] = av.x;
            As[nb][ac4 * 4 + 1][ar] = av.y;
            As[nb][ac4 * 4 + 2][ar] = av.z;
            As[nb][ac4 * 4 + 3][ar] = av.w;
            *(float4*)&Bs[nb][br][bc4 * 4]      = bv0;
            *(float4*)&Bs[nb][br][64 + bc4 * 4] = bv1;
            __syncthreads();
            buf = nb;
        }
    }

    float* qdst = g_qp[blockIdx.z];
#pragma unroll
    for (int i = 0; i < 4; i++) {
        int row = row0 + ty * 4 + i;
        float4 v0, v1;
        UNPACK_F32X2(v0.x, v0.y, acc2[i][0]);
        UNPACK_F32X2(v0.z, v0.w, acc2[i][1]);
        UNPACK_F32X2(v1.x, v1.y, acc2[i][2]);
        UNPACK_F32X2(v1.z, v1.w, acc2[i][3]);
        *(float4*)&qdst[(size_t)row * N + col0 + tx * 8]     = v0;
        *(float4*)&qdst[(size_t)row * N + col0 + tx * 8 + 4] = v1;
    }
}

// =====================================================================
// Kernel 2: sim = q . keys (Kahan), dual top-8, 64-combine, final top-8
// q is reconstructed as sum of 4 split-K partials at tile load.
// =====================================================================
#define K2_SMEM (65536 + 32 * 132 * 4 + 32 * 258 * 4)

__global__ __launch_bounds__(256) void router_kernel(const float* __restrict__ keys) {
    extern __shared__ float smem[];
    float* ks = smem;               // [2][128][64]  16384 floats
    float* qs = ks + 16384;         // [32][132]      4224 floats
    float* sm = qs + 32 * 132;      // [32][2][129]   8256 floats

    int h    = blockIdx.y;
    int tok0 = blockIdx.x * 32;
    int tid  = threadIdx.x;

    // ---- load keys for this head: keys[h][k][s][dk] -> ks[s][k][dk]
    const float4* kg = (const float4*)keys;
    float4* ks4 = (float4*)ks;
#pragma unroll
    for (int i = 0; i < 16; i++) {
        int u = tid + i * 256;          // 4096 float4s
        int dk4 = u & 15;
        int s   = (u >> 4) & 1;
        int k   = u >> 5;
        ks4[(s * 128 + k) * 16 + dk4] = kg[((h * 128 + k) * 2 + s) * 16 + dk4];
    }

    // ---- load q tile (sum of split-K partials, fixed order): -> qs[t][c]
    const float4* qg0 = (const float4*)g_qp[0];
    const float4* qg1 = (const float4*)g_qp[1];
    const float4* qg2 = (const float4*)g_qp[2];
    const float4* qg3 = (const float4*)g_qp[3];
    float4* qs4 = (float4*)qs;
#pragma unroll
    for (int i = 0; i < 4; i++) {
        int u = tid + i * 256;          // 1024 float4s
        int c4 = u & 31;
        int t  = u >> 5;
        size_t gidx = (size_t)(tok0 + t) * 128 + h * 32 + c4;
        float4 a = qg0[gidx], b = qg1[gidx], cc = qg2[gidx], dd = qg3[gidx];
        float4 r;
        r.x = ((a.x + b.x) + cc.x) + dd.x;
        r.y = ((a.y + b.y) + cc.y) + dd.y;
        r.z = ((a.z + b.z) + cc.z) + dd.z;
        r.w = ((a.w + b.w) + cc.w) + dd.w;
        qs4[t * 33 + c4] = r;
    }
    __syncthreads();

    // ---- sims: warp w: side=w>>2, keys [(w&3)*32, +32), lane = token
    int w = tid >> 5, lane = tid & 31;
    int side  = w >> 2;
    int kbase = (w & 3) * 32;
    const float4* qrow = (const float4*)qs + lane * 33 + side * 16;
    for (int kk = 0; kk < 32; kk++) {
        int k = kbase + kk;
        const float4* krow = (const float4*)ks + (side * 128 + k) * 16;
        float acc = 0.f, comp = 0.f;
#pragma unroll
        for (int c4 = 0; c4 < 16; c4++) {
            float4 kv = krow[c4];   // broadcast across lanes
            float4 qv = qrow[c4];   // conflict-free (stride 33 f4)
            float term = kv.x * qv.x + kv.y * qv.y + kv.z * qv.z + kv.w * qv.w;
            float y = term - comp;
            float t = acc + y;
            comp = (t - acc) - y;
            acc = t;
        }
        sm[lane * 258 + side * 129 + k] = acc;
    }
    __syncthreads();

    // ---- top-k (32 threads, one token each; stable like jax.lax.top_k)
    if (tid < 32) {
        const float NEG = -3.4e38f;
        float s1[TOPK], s2[TOPK], fs[TOPK];
        int   i1[TOPK], i2[TOPK], fi[TOPK];
#pragma unroll
        for (int r = 0; r < TOPK; r++) { s1[r] = NEG; s2[r] = NEG; fs[r] = NEG; i1[r] = 0; i2[r] = 0; fi[r] = 0; }

        const float* row1 = sm + tid * 258;
        const float* row2 = row1 + 129;
        for (int k = 0; k < NK; k++) {
            float v = row1[k];
            if (v > s1[TOPK - 1]) {
                int p = TOPK - 1;
                while (p > 0 && v > s1[p - 1]) { s1[p] = s1[p - 1]; i1[p] = i1[p - 1]; p--; }
                s1[p] = v; i1[p] = k;
            }
        }
        for (int k = 0; k < NK; k++) {
            float v = row2[k];
            if (v > s2[TOPK - 1]) {
                int p = TOPK - 1;
                while (p > 0 && v > s2[p - 1]) { s2[p] = s2[p - 1]; i2[p] = i2[p - 1]; p--; }
                s2[p] = v; i2[p] = k;
            }
        }
        // combine K*K in flattened order i*K+j (matches jax reshape/stability)
        for (int i = 0; i < TOPK; i++) {
            for (int j = 0; j < TOPK; j++) {
                float v = s1[i] + s2[j];
                if (v > fs[TOPK - 1]) {
                    int idx = i1[i] * NK + i2[j];
                    int p = TOPK - 1;
                    while (p > 0 && v > fs[p - 1]) { fs[p] = fs[p - 1]; fi[p] = fi[p - 1]; p--; }
                    fs[p] = v; fi[p] = idx;
                }
            }
        }
        int base = ((tok0 + tid) * H + h) * TOPK;
#pragma unroll
        for (int r = 0; r < TOPK; r++) {
            g_scores[base + r]  = fs[r];
            g_indices[base + r] = fi[r];
        }
    }
}

// =====================================================================
// Kernel 3: per-token expert compute (v3: 2 tokens/block, 256 threads)
// hidden = silu(x . e_down[idx]) * relu(score);  out = sum hidden * e_up[idx]
// =====================================================================
__global__ __launch_bounds__(256) void expert_kernel(const float* __restrict__ x,
                                                     const float* __restrict__ e_down,
                                                     const float* __restrict__ e_up,
                                                     float* __restrict__ out) {
    __shared__ float xs[2 * D];           // 16 KB (2 tokens)
    __shared__ float hid[2][H * TOPK];
    __shared__ int   eidx[2][H * TOPK];

    int tok0 = blockIdx.x * 2;
    int tid  = threadIdx.x;

    // load both token x rows (1024 float4)
    const float4* xg = (const float4*)(x + (size_t)tok0 * D);
    float4* xs4 = (float4*)xs;
#pragma unroll
    for (int i = 0; i < 4; i++) xs4[tid + i * 256] = xg[tid + i * 256];
    if (tid < 64) eidx[tid >> 5][tid & 31] = g_indices[tok0 * 32 + tid];
    __syncthreads();

    int w = tid >> 5, lane = tid & 31;
    int t = w & 1;                 // token within pair
    int ebase = (w >> 1) * 8;      // 8 experts per warp
    const float4* xrow = xs4 + t * 512;

    // ---- down: 8 expert-dots per warp, independent load streams
#pragma unroll
    for (int je = 0; je < 8; je++) {
        int e = ebase + je;
        size_t idx = (size_t)eidx[t][e];
        const float4* er = (const float4*)(e_down + idx * D);
        float acc0 = 0.f, acc1 = 0.f;
#pragma unroll
        for (int i = 0; i < 16; i += 2) {
            float4 ev0 = er[lane + 32 * i];
            float4 ev1 = er[lane + 32 * (i + 1)];
            float4 qv0 = xrow[lane + 32 * i];
            float4 qv1 = xrow[lane + 32 * (i + 1)];
            acc0 += ev0.x * qv0.x + ev0.y * qv0.y + ev0.z * qv0.z + ev0.w * qv0.w;
            acc1 += ev1.x * qv1.x + ev1.y * qv1.y + ev1.z * qv1.z + ev1.w * qv1.w;
        }
        float acc = acc0 + acc1;
#pragma unroll
        for (int o = 16; o > 0; o >>= 1) acc += __shfl_xor_sync(0xffffffffu, acc, o);
        if (lane == 0) {
            float sc = g_scores[(tok0 + t) * 32 + e];
            float g  = acc / (1.f + __expf(-acc));     // silu (value-only path)
            hid[t][e] = g * fmaxf(sc, 0.f);            // * relu(score)
        }
    }
    __syncthreads();

    // ---- up: each thread owns slots (tid, tid+256) for BOTH tokens
    float4 a00 = make_float4(0, 0, 0, 0), a01 = make_float4(0, 0, 0, 0);
    float4 a10 = make_float4(0, 0, 0, 0), a11 = make_float4(0, 0, 0, 0);
    const float4* up4 = (const float4*)e_up;
#pragma unroll
    for (int e = 0; e < 32; e++) {
        float g0 = hid[0][e];
        float g1 = hid[1][e];
        const float4* r0 = up4 + (size_t)eidx[0][e] * 512;
        const float4* r1 = up4 + (size_t)eidx[1][e] * 512;
        float4 u00 = r0[tid], u01 = r0[tid + 256];
        float4 u10 = r1[tid], u11 = r1[tid + 256];
        a00.x += g0 * u00.x; a00.y += g0 * u00.y; a00.z += g0 * u00.z; a00.w += g0 * u00.w;
        a01.x += g0 * u01.x; a01.y += g0 * u01.y; a01.z += g0 * u01.z; a01.w += g0 * u01.w;
        a10.x += g1 * u10.x; a10.y += g1 * u10.y; a10.z += g1 * u10.z; a10.w += g1 * u10.w;
        a11.x += g1 * u11.x; a11.y += g1 * u11.y; a11.z += g1 * u11.z; a11.w += g1 * u11.w;
    }
    float4* og = (float4*)(out + (size_t)tok0 * D);
    og[tid]        = a00;
    og[tid + 256]  = a01;
    og[tid + 512]  = a10;
    og[tid + 768]  = a11;
}

// =====================================================================
// launch
// =====================================================================
extern "C" void kernel_launch(void* const* d_in, const int* in_sizes, int n_in,
                              void* d_out, int out_size) {
    const float* x      = (const float*)d_in[0];
    const float* Wq     = (const float*)d_in[1];
    const float* keys   = (const float*)d_in[2];
    const float* e_down = (const float*)d_in[3];
    const float* e_up   = (const float*)d_in[4];
    float* out = (float*)d_out;

    cudaFuncSetAttribute(router_kernel, cudaFuncAttributeMaxDynamicSharedMemorySize, K2_SMEM);

    qproj_kernel<<<dim3(QN / 128, BT / 64, KSPLITS), 256>>>(x, Wq);
    router_kernel<<<dim3(BT / 32, H), 256, K2_SMEM>>>(keys);
    expert_kernel<<<BT / 2, 256>>>(x, e_down, e_up, out);
}

// round 17
// speedup vs baseline: 1.1531x; 1.1309x over previous
#include <cuda_runtime.h>
#include <cuda_bf16.h>
#include <math.h>

// Problem constants
#define BT   2048      // B*T
#define D    2048
#define H    4
#define TOPK 8
#define DK   64
#define NE   16384     // E
#define NK   128
#define QN   512       // 2*H*DK

// ---- packed f32x2 ops (Blackwell sm_103a; FFMA2 only reachable via PTX) ----
#define FMA_F32X2(d, a, b, c) \
    asm("fma.rn.f32x2 %0, %1, %2, %3;" : "=l"(d) : "l"(a), "l"(b), "l"(c))
#define ADD_F32X2(d, a, b) \
    asm("add.rn.f32x2 %0, %1, %2;" : "=l"(d) : "l"(a), "l"(b))
#define SUB_F32X2(d, a, b) \
    asm("sub.rn.f32x2 %0, %1, %2;" : "=l"(d) : "l"(a), "l"(b))
#define PACK_F32X2(out, lo, hi) \
    asm("mov.b64 %0, {%1, %2};" : "=l"(out) : "f"(lo), "f"(hi))
#define UNPACK_F32X2(lo, hi, in) \
    asm("mov.b64 {%0, %1}, %2;" : "=f"(lo), "=f"(hi) : "l"(in))

// ---------------- scratch (device globals, no alloc) ----------------
__device__ float g_qp[2][BT * QN];         // split-K partials, 8 MB
__device__ float g_scores[BT * H * TOPK];  // 256 KB
__device__ int   g_indices[BT * H * TOPK];

// =====================================================================
// Kernel 1: q = x @ Wq   (FP32 SGEMM, M=2048, N=512, K=2048)
// Split-K=2 (grid.z), BM=64 BN=64 BK=16, 256 threads, 4x4/thread.
// Inner product in packed f32x2 (FFMA2), Kahan chunk merge in f32x2.
// =====================================================================
__global__ __launch_bounds__(256) void qproj_kernel(const float* __restrict__ A,
                                                    const float* __restrict__ B) {
    const int Kd = D, N = QN;
    const int KSPLIT = Kd / 2;       // 1024
    const int NCH = KSPLIT / 16;     // 64 chunks

    __shared__ float As[2][16][68];  // transposed, padded
    __shared__ float Bs[2][16][64];

    int tid = threadIdx.x;
    int tx = tid & 15;               // col group (4 cols each)
    int ty = tid >> 4;               // row group (4 rows each)
    int row0 = blockIdx.y * 64;
    int col0 = blockIdx.x * 64;
    int kbase = blockIdx.z * KSPLIT;

    int ar = tid >> 2, ac4 = tid & 3;
    int br = tid >> 4, bc4 = tid & 15;

    const float* Aptr = A + (size_t)(row0 + ar) * Kd + kbase + ac4 * 4;
    const float* Bptr = B + (size_t)(kbase + br) * N + col0 + bc4 * 4;

    // accumulators: 4 rows x 2 column-pairs, packed f32x2
    unsigned long long acc2[4][2], cmp2[4][2];
#pragma unroll
    for (int i = 0; i < 4; i++)
#pragma unroll
        for (int jp = 0; jp < 2; jp++) { acc2[i][jp] = 0ull; cmp2[i][jp] = 0ull; }

    // preload chunk 0 into buffer 0
    float4 av = *(const float4*)Aptr;
    float4 bv = *(const float4*)Bptr;
    As[0][ac4 * 4 + 0][ar] = av.x;
    As[0][ac4 * 4 + 1][ar] = av.y;
    As[0][ac4 * 4 + 2][ar] = av.z;
    As[0][ac4 * 4 + 3][ar] = av.w;
    *(float4*)&Bs[0][br][bc4 * 4] = bv;
    __syncthreads();

    int buf = 0;
    for (int c = 0; c < NCH; c++) {
        // prefetch next chunk into registers (overlaps with compute)
        if (c + 1 < NCH) {
            Aptr += 16;
            Bptr += (size_t)16 * N;
            av = *(const float4*)Aptr;
            bv = *(const float4*)Bptr;
        }

        unsigned long long sub2[4][2];
#pragma unroll
        for (int i = 0; i < 4; i++)
#pragma unroll
            for (int jp = 0; jp < 2; jp++) sub2[i][jp] = 0ull;

#pragma unroll
        for (int k = 0; k < 16; k++) {
            float4 a = *(const float4*)&As[buf][k][ty * 4];
            const unsigned long long* bp = (const unsigned long long*)&Bs[buf][k][tx * 4];
            unsigned long long b0 = bp[0], b1 = bp[1];

            unsigned long long ax, ay, az, aw;
            PACK_F32X2(ax, a.x, a.x);
            PACK_F32X2(ay, a.y, a.y);
            PACK_F32X2(az, a.z, a.z);
            PACK_F32X2(aw, a.w, a.w);

            FMA_F32X2(sub2[0][0], ax, b0, sub2[0][0]);
            FMA_F32X2(sub2[0][1], ax, b1, sub2[0][1]);
            FMA_F32X2(sub2[1][0], ay, b0, sub2[1][0]);
            FMA_F32X2(sub2[1][1], ay, b1, sub2[1][1]);
            FMA_F32X2(sub2[2][0], az, b0, sub2[2][0]);
            FMA_F32X2(sub2[2][1], az, b1, sub2[2][1]);
            FMA_F32X2(sub2[3][0], aw, b0, sub2[3][0]);
            FMA_F32X2(sub2[3][1], aw, b1, sub2[3][1]);
        }

        // Kahan merge of chunk sums (packed, per-lane identical to scalar)
#pragma unroll
        for (int i = 0; i < 4; i++)
#pragma unroll
            for (int jp = 0; jp < 2; jp++) {
                unsigned long long y, t, d;
                SUB_F32X2(y, sub2[i][jp], cmp2[i][jp]);   // y = sub - cmp
                ADD_F32X2(t, acc2[i][jp], y);             // t = acc + y
                SUB_F32X2(d, t, acc2[i][jp]);             // d = t - acc
                SUB_F32X2(cmp2[i][jp], d, y);             // cmp = d - y
                acc2[i][jp] = t;
            }

        // stage prefetched chunk into the other buffer
        if (c + 1 < NCH) {
            int nb = buf ^ 1;
            As[nb][ac4 * 4 + 0][ar] = av.x;
            As[nb][ac4 * 4 + 1][ar] = av.y;
            As[nb][ac4 * 4 + 2][ar] = av.z;
            As[nb][ac4 * 4 + 3][ar] = av.w;
            *(float4*)&Bs[nb][br][bc4 * 4] = bv;
            __syncthreads();
            buf = nb;
        }
    }

    float* qdst = g_qp[blockIdx.z];
#pragma unroll
    for (int i = 0; i < 4; i++) {
        int row = row0 + ty * 4 + i;
        float4 v;
        UNPACK_F32X2(v.x, v.y, acc2[i][0]);
        UNPACK_F32X2(v.z, v.w, acc2[i][1]);
        *(float4*)&qdst[(size_t)row * N + col0 + tx * 4] = v;
    }
}

// =====================================================================
// Kernel 2: sim = q . keys (Kahan), dual top-8, 64-combine, final top-8
// q is reconstructed as g_qp[0] + g_qp[1] at tile load.
// =====================================================================
#define K2_SMEM (65536 + 32 * 132 * 4 + 32 * 258 * 4)

__global__ __launch_bounds__(256) void router_kernel(const float* __restrict__ keys) {
    extern __shared__ float smem[];
    float* ks = smem;               // [2][128][64]  16384 floats
    float* qs = ks + 16384;         // [32][132]      4224 floats
    float* sm = qs + 32 * 132;      // [32][2][129]   8256 floats

    int h    = blockIdx.y;
    int tok0 = blockIdx.x * 32;
    int tid  = threadIdx.x;

    // ---- load keys for this head: keys[h][k][s][dk] -> ks[s][k][dk]
    const float4* kg = (const float4*)keys;
    float4* ks4 = (float4*)ks;
#pragma unroll
    for (int i = 0; i < 16; i++) {
        int u = tid + i * 256;          // 4096 float4s
        int dk4 = u & 15;
        int s   = (u >> 4) & 1;
        int k   = u >> 5;
        ks4[(s * 128 + k) * 16 + dk4] = kg[((h * 128 + k) * 2 + s) * 16 + dk4];
    }

    // ---- load q tile (sum of split-K partials): -> qs[t][c] (stride 132)
    const float4* qg0 = (const float4*)g_qp[0];
    const float4* qg1 = (const float4*)g_qp[1];
    float4* qs4 = (float4*)qs;
#pragma unroll
    for (int i = 0; i < 4; i++) {
        int u = tid + i * 256;          // 1024 float4s
        int c4 = u & 31;
        int t  = u >> 5;
        size_t gidx = (size_t)(tok0 + t) * 128 + h * 32 + c4;
        float4 a = qg0[gidx], b = qg1[gidx];
        qs4[t * 33 + c4] = make_float4(a.x + b.x, a.y + b.y, a.z + b.z, a.w + b.w);
    }
    __syncthreads();

    // ---- sims: warp w: side=w>>2, keys [(w&3)*32, +32), lane = token
    int w = tid >> 5, lane = tid & 31;
    int side  = w >> 2;
    int kbase = (w & 3) * 32;
    const float4* qrow = (const float4*)qs + lane * 33 + side * 16;
    for (int kk = 0; kk < 32; kk++) {
        int k = kbase + kk;
        const float4* krow = (const float4*)ks + (side * 128 + k) * 16;
        float acc = 0.f, comp = 0.f;
#pragma unroll
        for (int c4 = 0; c4 < 16; c4++) {
            float4 kv = krow[c4];   // broadcast across lanes
            float4 qv = qrow[c4];   // conflict-free (stride 33 f4)
            float term = kv.x * qv.x + kv.y * qv.y + kv.z * qv.z + kv.w * qv.w;
            float y = term - comp;
            float t = acc + y;
            comp = (t - acc) - y;
            acc = t;
        }
        sm[lane * 258 + side * 129 + k] = acc;
    }
    __syncthreads();

    // ---- top-k (32 threads, one token each; stable like jax.lax.top_k)
    if (tid < 32) {
        const float NEG = -3.4e38f;
        float s1[TOPK], s2[TOPK], fs[TOPK];
        int   i1[TOPK], i2[TOPK], fi[TOPK];
#pragma unroll
        for (int r = 0; r < TOPK; r++) { s1[r] = NEG; s2[r] = NEG; fs[r] = NEG; i1[r] = 0; i2[r] = 0; fi[r] = 0; }

        const float* row1 = sm + tid * 258;
        const float* row2 = row1 + 129;
        for (int k = 0; k < NK; k++) {
            float v = row1[k];
            if (v > s1[TOPK - 1]) {
                int p = TOPK - 1;
                while (p > 0 && v > s1[p - 1]) { s1[p] = s1[p - 1]; i1[p] = i1[p - 1]; p--; }
                s1[p] = v; i1[p] = k;
            }
        }
        for (int k = 0; k < NK; k++) {
            float v = row2[k];
            if (v > s2[TOPK - 1]) {
                int p = TOPK - 1;
                while (p > 0 && v > s2[p - 1]) { s2[p] = s2[p - 1]; i2[p] = i2[p - 1]; p--; }
                s2[p] = v; i2[p] = k;
            }
        }
        // combine K*K in flattened order i*K+j (matches jax reshape/stability)
        for (int i = 0; i < TOPK; i++) {
            for (int j = 0; j < TOPK; j++) {
                float v = s1[i] + s2[j];
                if (v > fs[TOPK - 1]) {
                    int idx = i1[i] * NK + i2[j];
                    int p = TOPK - 1;
                    while (p > 0 && v > fs[p - 1]) { fs[p] = fs[p - 1]; fi[p] = fi[p - 1]; p--; }
                    fs[p] = v; fi[p] = idx;
                }
            }
        }
        int base = ((tok0 + tid) * H + h) * TOPK;
#pragma unroll
        for (int r = 0; r < TOPK; r++) {
            g_scores[base + r]  = fs[r];
            g_indices[base + r] = fi[r];
        }
    }
}

// =====================================================================
// Kernel 3: per-token expert compute (v5: 2 tokens/block, 256 threads,
// paired expert streams for 2x MLP)
// hidden = silu(x . e_down[idx]) * relu(score);  out = sum hidden * e_up[idx]
// =====================================================================
__global__ __launch_bounds__(256) void expert_kernel(const float* __restrict__ x,
                                                     const float* __restrict__ e_down,
                                                     const float* __restrict__ e_up,
                                                     float* __restrict__ out) {
    __shared__ float xs[2 * D];           // 16 KB (2 tokens)
    __shared__ float hid[2][H * TOPK];
    __shared__ int   eidx[2][H * TOPK];

    int tok0 = blockIdx.x * 2;
    int tid  = threadIdx.x;

    // load both token x rows (1024 float4)
    const float4* xg = (const float4*)(x + (size_t)tok0 * D);
    float4* xs4 = (float4*)xs;
#pragma unroll
    for (int i = 0; i < 4; i++) xs4[tid + i * 256] = xg[tid + i * 256];
    if (tid < 64) eidx[tid >> 5][tid & 31] = g_indices[tok0 * 32 + tid];
    __syncthreads();

    int w = tid >> 5, lane = tid & 31;
    int t = w & 1;                 // token within pair
    int ebase = (w >> 1) * 8;      // 8 experts per warp
    const float4* xrow = xs4 + t * 512;

    // ---- down: expert PAIRS per warp -> two independent row streams
#pragma unroll
    for (int je = 0; je < 8; je += 2) {
        int eA = ebase + je, eB = eA + 1;
        const float4* erA = (const float4*)(e_down + (size_t)eidx[t][eA] * D);
        const float4* erB = (const float4*)(e_down + (size_t)eidx[t][eB] * D);
        float aA0 = 0.f, aA1 = 0.f, aB0 = 0.f, aB1 = 0.f;
#pragma unroll
        for (int i = 0; i < 16; i += 2) {
            float4 qv0 = xrow[lane + 32 * i];
            float4 qv1 = xrow[lane + 32 * (i + 1)];
            float4 eA0 = erA[lane + 32 * i];
            float4 eA1 = erA[lane + 32 * (i + 1)];
            float4 eB0 = erB[lane + 32 * i];
            float4 eB1 = erB[lane + 32 * (i + 1)];
            aA0 += eA0.x * qv0.x + eA0.y * qv0.y + eA0.z * qv0.z + eA0.w * qv0.w;
            aA1 += eA1.x * qv1.x + eA1.y * qv1.y + eA1.z * qv1.z + eA1.w * qv1.w;
            aB0 += eB0.x * qv0.x + eB0.y * qv0.y + eB0.z * qv0.z + eB0.w * qv0.w;
            aB1 += eB1.x * qv1.x + eB1.y * qv1.y + eB1.z * qv1.z + eB1.w * qv1.w;
        }
        float accA = aA0 + aA1;
        float accB = aB0 + aB1;
#pragma unroll
        for (int o = 16; o > 0; o >>= 1) {
            accA += __shfl_xor_sync(0xffffffffu, accA, o);
            accB += __shfl_xor_sync(0xffffffffu, accB, o);
        }
        if (lane == 0) {
            float scA = g_scores[(tok0 + t) * 32 + eA];
            float scB = g_scores[(tok0 + t) * 32 + eB];
            float gA  = accA / (1.f + __expf(-accA));
            float gB  = accB / (1.f + __expf(-accB));
            hid[t][eA] = gA * fmaxf(scA, 0.f);
            hid[t][eB] = gB * fmaxf(scB, 0.f);
        }
    }
    __syncthreads();

    // ---- up: 2 experts x 2 tokens per step; 8 loads hoisted ahead of FMAs
    float4 a00 = make_float4(0, 0, 0, 0), a01 = make_float4(0, 0, 0, 0);
    float4 a10 = make_float4(0, 0, 0, 0), a11 = make_float4(0, 0, 0, 0);
    const float4* up4 = (const float4*)e_up;
#pragma unroll
    for (int e = 0; e < 32; e += 2) {
        float g0a = hid[0][e],     g1a = hid[1][e];
        float g0b = hid[0][e + 1], g1b = hid[1][e + 1];
        const float4* r0a = up4 + (size_t)eidx[0][e] * 512;
        const float4* r1a = up4 + (size_t)eidx[1][e] * 512;
        const float4* r0b = up4 + (size_t)eidx[0][e + 1] * 512;
        const float4* r1b = up4 + (size_t)eidx[1][e + 1] * 512;
        float4 u00a = r0a[tid], u01a = r0a[tid + 256];
        float4 u10a = r1a[tid], u11a = r1a[tid + 256];
        float4 u00b = r0b[tid], u01b = r0b[tid + 256];
        float4 u10b = r1b[tid], u11b = r1b[tid + 256];
        // e (a) first, then e+1 (b): same accumulation order as v3
        a00.x += g0a * u00a.x; a00.y += g0a * u00a.y; a00.z += g0a * u00a.z; a00.w += g0a * u00a.w;
        a01.x += g0a * u01a.x; a01.y += g0a * u01a.y; a01.z += g0a * u01a.z; a01.w += g0a * u01a.w;
        a10.x += g1a * u10a.x; a10.y += g1a * u10a.y; a10.z += g1a * u10a.z; a10.w += g1a * u10a.w;
        a11.x += g1a * u11a.x; a11.y += g1a * u11a.y; a11.z += g1a * u11a.z; a11.w += g1a * u11a.w;
        a00.x += g0b * u00b.x; a00.y += g0b * u00b.y; a00.z += g0b * u00b.z; a00.w += g0b * u00b.w;
        a01.x += g0b * u01b.x; a01.y += g0b * u01b.y; a01.z += g0b * u01b.z; a01.w += g0b * u01b.w;
        a10.x += g1b * u10b.x; a10.y += g1b * u10b.y; a10.z += g1b * u10b.z; a10.w += g1b * u10b.w;
        a11.x += g1b * u11b.x; a11.y += g1b * u11b.y; a11.z += g1b * u11b.z; a11.w += g1b * u11b.w;
    }
    float4* og = (float4*)(out + (size_t)tok0 * D);
    og[tid]        = a00;
    og[tid + 256]  = a01;
    og[tid + 512]  = a10;
    og[tid + 768]  = a11;
}

// =====================================================================
// launch
// =====================================================================
extern "C" void kernel_launch(void* const* d_in, const int* in_sizes, int n_in,
                              void* d_out, int out_size) {
    const float* x      = (const float*)d_in[0];
    const float* Wq     = (const float*)d_in[1];
    const float* keys   = (const float*)d_in[2];
    const float* e_down = (const float*)d_in[3];
    const float* e_up   = (const float*)d_in[4];
    float* out = (float*)d_out;

    cudaFuncSetAttribute(router_kernel, cudaFuncAttributeMaxDynamicSharedMemorySize, K2_SMEM);

    qproj_kernel<<<dim3(QN / 64, BT / 64, 2), 256>>>(x, Wq);
    router_kernel<<<dim3(BT / 32, H), 256, K2_SMEM>>>(keys);
    expert_kernel<<<BT / 2, 256>>>(x, e_down, e_up, out);
}